// round 7
// baseline (speedup 1.0000x reference)
#include <cuda_runtime.h>
#include <cuda_bf16.h>

// Problem constants (from reference setup_inputs)
#define IN_F  512
#define HID   64
#define OUTF  7
#define MAXN  50000
#define MAXE  1600000

// ---------------- scratch (device globals; no allocation allowed) -----------
__device__ __align__(16) int   g_deg[MAXN];
__device__ __align__(16) float g_dinv[MAXN];
__device__ __align__(16) float g_norm[MAXE];
__device__ __align__(16) int   g_s32[MAXE];
__device__ __align__(16) int   g_d32[MAXE];
__device__ __align__(16) float g_h[MAXN * HID];     // x @ W1
__device__ __align__(16) float g_agg[MAXN * HID];   // layer1 aggregation
__device__ __align__(16) float g_h2[MAXN * 8];      // relu(agg+b1) @ W2, padded to 8
__device__ __align__(16) float g_agg2[MAXN * 8];    // layer2 aggregation, padded
__device__ int g_is32;

// ---------------- vector reduction (no-return atomic add) -------------------
__device__ __forceinline__ void red_add_v4(float* addr, float4 v) {
    asm volatile("red.global.add.v4.f32 [%0], {%1, %2, %3, %4};"
                 :: "l"(addr), "f"(v.x), "f"(v.y), "f"(v.z), "f"(v.w)
                 : "memory");
}

// ---------------- edge dtype detection --------------------------------------
// If the edge buffer is really int64, every entry is in [0, N). If it is int32
// data viewed as int64, the high word is a random src/dst value, so values are
// >= 2^32 almost surely within the first 2048 words.
__global__ void k_detect(const long long* __restrict__ ei, int E, int N) {
    if (threadIdx.x == 0) g_is32 = 0;
    __syncthreads();
    int cnt = min(2 * E, 2048);
    int bad = 0;
    for (int i = threadIdx.x; i < cnt; i += blockDim.x) {
        long long v = ei[i];
        if (v < 0 || v >= (long long)N) bad = 1;
    }
    if (bad) atomicExch(&g_is32, 1);
}

__global__ void k_extract(const void* __restrict__ eiv, int E) {
    int e = blockIdx.x * blockDim.x + threadIdx.x;
    if (e >= E) return;
    if (g_is32) {
        const int* ei = (const int*)eiv;
        g_s32[e] = ei[e];
        g_d32[e] = ei[E + e];
    } else {
        const long long* ei = (const long long*)eiv;
        g_s32[e] = (int)ei[e];
        g_d32[e] = (int)ei[E + e];
    }
}

// deg starts at 1 (the self loop)
__global__ void k_deg_init(int N) {
    int i = blockIdx.x * blockDim.x + threadIdx.x;
    if (i < N) g_deg[i] = 1;
}

__global__ void k_deg_count(int E) {
    int e = blockIdx.x * blockDim.x + threadIdx.x;
    if (e < E) atomicAdd(&g_deg[g_d32[e]], 1);
}

__global__ void k_dinv(int N) {
    int i = blockIdx.x * blockDim.x + threadIdx.x;
    if (i < N) g_dinv[i] = rsqrtf((float)g_deg[i]);
}

__global__ void k_norm(int E) {
    int e = blockIdx.x * blockDim.x + threadIdx.x;
    if (e < E) g_norm[e] = g_dinv[g_s32[e]] * g_dinv[g_d32[e]];
}

// ---------------- GEMM1: h = x @ W1  (N x 512 @ 512 x 64) -------------------
// 64x64 tile per block, BK=32, 256 threads, 4x4 accum per thread.
__global__ __launch_bounds__(256) void k_gemm1(const float* __restrict__ x,
                                               const float* __restrict__ W1,
                                               int N) {
    __shared__ float xs[64][32];
    __shared__ float ws[32][64];
    int tid = threadIdx.x;
    int tx = tid & 15, ty = tid >> 4;
    int row0 = blockIdx.x * 64;
    float acc[4][4] = {};

    for (int k0 = 0; k0 < IN_F; k0 += 32) {
        // load x tile: 64x32 = 512 float4, 2 per thread
        #pragma unroll
        for (int i = 0; i < 2; i++) {
            int f = tid * 2 + i;
            int r = f >> 3, c4 = (f & 7) * 4;
            int gr = row0 + r;
            float4 v = make_float4(0.f, 0.f, 0.f, 0.f);
            if (gr < N) v = *(const float4*)&x[(size_t)gr * IN_F + k0 + c4];
            *(float4*)&xs[r][c4] = v;
        }
        // load W1 tile: 32x64 = 512 float4, 2 per thread
        #pragma unroll
        for (int i = 0; i < 2; i++) {
            int f = tid * 2 + i;
            int r = f >> 4, c4 = (f & 15) * 4;
            *(float4*)&ws[r][c4] = *(const float4*)&W1[(k0 + r) * HID + c4];
        }
        __syncthreads();
        #pragma unroll
        for (int k = 0; k < 32; k++) {
            float a[4];
            #pragma unroll
            for (int i = 0; i < 4; i++) a[i] = xs[ty * 4 + i][k];
            float4 bv = *(float4*)&ws[k][tx * 4];
            float b[4] = {bv.x, bv.y, bv.z, bv.w};
            #pragma unroll
            for (int i = 0; i < 4; i++)
                #pragma unroll
                for (int j = 0; j < 4; j++) acc[i][j] += a[i] * b[j];
        }
        __syncthreads();
    }
    #pragma unroll
    for (int i = 0; i < 4; i++) {
        int gr = row0 + ty * 4 + i;
        if (gr < N)
            *(float4*)&g_h[(size_t)gr * HID + tx * 4] =
                make_float4(acc[i][0], acc[i][1], acc[i][2], acc[i][3]);
    }
}

// agg init with self-loop contribution: agg[i] = h[i] * dinv[i]^2
__global__ void k_initagg(int N) {
    int idx = blockIdx.x * blockDim.x + threadIdx.x;  // over N*16 float4s
    if (idx >= N * 16) return;
    int row = idx >> 4;
    float s = g_dinv[row]; s = s * s;
    float4 v = *(float4*)&g_h[idx * 4];
    v.x *= s; v.y *= s; v.z *= s; v.w *= s;
    *(float4*)&g_agg[idx * 4] = v;
}

// 16 threads per edge, one float4 each: agg[dst] += h[src] * norm
__global__ void k_edge1(int E) {
    int idx = blockIdx.x * blockDim.x + threadIdx.x;
    if (idx >= E * 16) return;
    int e = idx >> 4, c = idx & 15;
    int s = g_s32[e], d = g_d32[e];
    float nm = g_norm[e];
    float4 v = *(const float4*)&g_h[s * HID + c * 4];
    v.x *= nm; v.y *= nm; v.z *= nm; v.w *= nm;
    red_add_v4(&g_agg[d * HID + c * 4], v);
}

// h2 = relu(agg + b1) @ W2, padded to 8 cols. 8 lanes cooperate per node.
__global__ __launch_bounds__(256) void k_layer2(const float* __restrict__ b1,
                                                const float* __restrict__ W2,
                                                int N) {
    __shared__ float w2s[HID * OUTF];
    __shared__ float b1s[HID];
    int tid = threadIdx.x;
    // BUGFIX (round 4): HID*OUTF = 448 > blockDim = 256. The old guarded
    // single store left w2s[256..447] uninitialized -> garbage layer-2 output.
    for (int i = tid; i < HID * OUTF; i += blockDim.x) w2s[i] = W2[i];
    if (tid < HID) b1s[tid] = b1[tid];
    __syncthreads();

    int gid = blockIdx.x * blockDim.x + tid;
    int n = gid >> 3;
    int lane = gid & 7;
    int n_eff = n < N ? n : N - 1;

    float acc[OUTF] = {};
    #pragma unroll
    for (int j = 0; j < 8; j++) {
        int k = lane + j * 8;
        float a = fmaxf(g_agg[n_eff * HID + k] + b1s[k], 0.f);
        #pragma unroll
        for (int o = 0; o < OUTF; o++) acc[o] += a * w2s[k * OUTF + o];
    }
    #pragma unroll
    for (int off = 4; off > 0; off >>= 1)
        #pragma unroll
        for (int o = 0; o < OUTF; o++)
            acc[o] += __shfl_down_sync(0xFFFFFFFF, acc[o], off, 8);

    if (n < N && lane == 0) {
        #pragma unroll
        for (int o = 0; o < OUTF; o++) g_h2[n * 8 + o] = acc[o];
        g_h2[n * 8 + 7] = 0.f;
    }
}

__global__ void k_initagg2(int N) {
    int idx = blockIdx.x * blockDim.x + threadIdx.x;  // over N*2 float4s
    if (idx >= N * 2) return;
    int row = idx >> 1;
    float s = g_dinv[row]; s = s * s;
    float4 v = *(float4*)&g_h2[idx * 4];
    v.x *= s; v.y *= s; v.z *= s; v.w *= s;
    *(float4*)&g_agg2[idx * 4] = v;
}

// 2 threads per edge
__global__ void k_edge2(int E) {
    int idx = blockIdx.x * blockDim.x + threadIdx.x;
    if (idx >= E * 2) return;
    int e = idx >> 1, c = idx & 1;
    int s = g_s32[e], d = g_d32[e];
    float nm = g_norm[e];
    float4 v = *(const float4*)&g_h2[s * 8 + c * 4];
    v.x *= nm; v.y *= nm; v.z *= nm; v.w *= nm;
    red_add_v4(&g_agg2[d * 8 + c * 4], v);
}

__global__ void k_final(const float* __restrict__ b2, float* __restrict__ out, int N) {
    int idx = blockIdx.x * blockDim.x + threadIdx.x;
    if (idx >= N * OUTF) return;
    int n = idx / OUTF, o = idx - n * OUTF;
    out[idx] = g_agg2[n * 8 + o] + b2[o];
}

// ---------------- launch -----------------------------------------------------
extern "C" void kernel_launch(void* const* d_in, const int* in_sizes, int n_in,
                              void* d_out, int out_size) {
    const float* x  = (const float*)d_in[0];
    const void*  ei = d_in[1];
    const float* W1 = (const float*)d_in[2];
    const float* b1 = (const float*)d_in[3];
    const float* W2 = (const float*)d_in[4];
    const float* b2 = (const float*)d_in[5];
    float* out = (float*)d_out;

    int N = in_sizes[0] / IN_F;
    int E = in_sizes[1] / 2;

    const int T = 256;
    k_detect<<<1, T>>>((const long long*)ei, E, N);
    k_extract<<<(E + T - 1) / T, T>>>(ei, E);
    k_deg_init<<<(N + T - 1) / T, T>>>(N);
    k_deg_count<<<(E + T - 1) / T, T>>>(E);
    k_dinv<<<(N + T - 1) / T, T>>>(N);
    k_norm<<<(E + T - 1) / T, T>>>(E);

    k_gemm1<<<(N + 63) / 64, T>>>(x, W1, N);
    k_initagg<<<(N * 16 + T - 1) / T, T>>>(N);
    k_edge1<<<(E * 16 + T - 1) / T, T>>>(E);

    k_layer2<<<(N * 8 + T - 1) / T, T>>>(b1, W2, N);
    k_initagg2<<<(N * 2 + T - 1) / T, T>>>(N);
    k_edge2<<<(E * 2 + T - 1) / T, T>>>(E);
    k_final<<<(N * OUTF + T - 1) / T, T>>>(b2, out, N);
}

// round 8
// speedup vs baseline: 1.4431x; 1.4431x over previous
#include <cuda_runtime.h>
#include <cuda_bf16.h>

// Problem constants (from reference setup_inputs)
#define IN_F  512
#define HID   64
#define OUTF  7
#define MAXN  50000
#define MAXE  1600000

// ---------------- scratch (device globals; no allocation allowed) -----------
__device__ __align__(16) int   g_deg[MAXN];     // degree incl. self loop
__device__ __align__(16) float g_dinv[MAXN];
__device__ __align__(16) int   g_off[MAXN];     // CSR row start (by dst)
__device__ __align__(16) int   g_cur[MAXN];     // scatter cursor
__device__ __align__(16) int   g_s32[MAXE];
__device__ __align__(16) int   g_d32[MAXE];
__device__ __align__(16) int   g_csrc[MAXE];    // CSR: src per slot
__device__ __align__(16) float g_cnrm[MAXE];    // CSR: norm per slot
__device__ __align__(16) float g_h[MAXN * HID]; // x @ W1
__device__ __align__(16) float g_h2[MAXN * 8];  // layer2 features, padded to 8
__device__ int g_is32;

// ---------------- edge dtype detection --------------------------------------
// If the edge buffer is really int64, every entry is in [0, N). If it is int32
// data viewed as int64, values are >= 2^32 (or negative) almost surely within
// the first 2048 words.
__global__ void k_detect(const long long* __restrict__ ei, int E, int N) {
    if (threadIdx.x == 0) g_is32 = 0;
    __syncthreads();
    int cnt = min(2 * E, 2048);
    int bad = 0;
    for (int i = threadIdx.x; i < cnt; i += blockDim.x) {
        long long v = ei[i];
        if (v < 0 || v >= (long long)N) bad = 1;
    }
    if (bad) atomicExch(&g_is32, 1);
}

// deg starts at 1 (the self loop)
__global__ void k_deg_init(int N) {
    int i = blockIdx.x * blockDim.x + threadIdx.x;
    if (i < N) g_deg[i] = 1;
}

// extract indices + degree histogram in one pass
__global__ void k_extract_deg(const void* __restrict__ eiv, int E) {
    int e = blockIdx.x * blockDim.x + threadIdx.x;
    if (e >= E) return;
    int s, d;
    if (g_is32) {
        const int* ei = (const int*)eiv;
        s = ei[e]; d = ei[E + e];
    } else {
        const long long* ei = (const long long*)eiv;
        s = (int)ei[e]; d = (int)ei[E + e];
    }
    g_s32[e] = s;
    g_d32[e] = d;
    atomicAdd(&g_deg[d], 1);
}

// single-block exclusive scan of (deg-1) -> g_off/g_cur, plus dinv.
// 1024 threads x 4 items per thread per iteration.
__global__ __launch_bounds__(1024) void k_scan_dinv(int N) {
    __shared__ int wsum[32];
    __shared__ int s_carry;
    int tid = threadIdx.x;
    int lane = tid & 31, warp = tid >> 5;
    if (tid == 0) s_carry = 0;
    __syncthreads();
    for (int base = 0; base < N; base += 1024 * 4) {
        int i0 = base + tid * 4;
        int d0 = 0, d1 = 0, d2 = 0, d3 = 0;
        if (i0 + 3 < N) {
            int4 dd = *(const int4*)&g_deg[i0];
            d0 = dd.x; d1 = dd.y; d2 = dd.z; d3 = dd.w;
        } else {
            if (i0     < N) d0 = g_deg[i0];
            if (i0 + 1 < N) d1 = g_deg[i0 + 1];
            if (i0 + 2 < N) d2 = g_deg[i0 + 2];
            if (i0 + 3 < N) d3 = g_deg[i0 + 3];
        }
        if (i0     < N) g_dinv[i0]     = rsqrtf((float)d0);
        if (i0 + 1 < N) g_dinv[i0 + 1] = rsqrtf((float)d1);
        if (i0 + 2 < N) g_dinv[i0 + 2] = rsqrtf((float)d2);
        if (i0 + 3 < N) g_dinv[i0 + 3] = rsqrtf((float)d3);
        int e0 = (i0     < N) ? d0 - 1 : 0;
        int e1 = (i0 + 1 < N) ? d1 - 1 : 0;
        int e2 = (i0 + 2 < N) ? d2 - 1 : 0;
        int e3 = (i0 + 3 < N) ? d3 - 1 : 0;
        int v = e0 + e1 + e2 + e3;
        // warp inclusive scan
        int x = v;
        #pragma unroll
        for (int off = 1; off < 32; off <<= 1) {
            int y = __shfl_up_sync(0xFFFFFFFFu, x, off);
            if (lane >= off) x += y;
        }
        if (lane == 31) wsum[warp] = x;
        __syncthreads();
        if (warp == 0) {
            int w = wsum[lane];
            #pragma unroll
            for (int off = 1; off < 32; off <<= 1) {
                int y = __shfl_up_sync(0xFFFFFFFFu, w, off);
                if (lane >= off) w += y;
            }
            wsum[lane] = w;
        }
        __syncthreads();
        int excl = x - v + (warp > 0 ? wsum[warp - 1] : 0) + s_carry;
        if (i0     < N) { g_off[i0]     = excl;            g_cur[i0]     = excl; }
        if (i0 + 1 < N) { g_off[i0 + 1] = excl + e0;       g_cur[i0 + 1] = excl + e0; }
        if (i0 + 2 < N) { g_off[i0 + 2] = excl + e0 + e1;  g_cur[i0 + 2] = excl + e0 + e1; }
        if (i0 + 3 < N) { g_off[i0 + 3] = excl + e0 + e1 + e2; g_cur[i0 + 3] = excl + e0 + e1 + e2; }
        __syncthreads();
        if (tid == 0) s_carry += wsum[31];
        __syncthreads();
    }
}

// bin edges by dst: CSR slot <- (src, norm)
__global__ void k_scatter(int E) {
    int e = blockIdx.x * blockDim.x + threadIdx.x;
    if (e >= E) return;
    int s = g_s32[e], d = g_d32[e];
    float nm = g_dinv[s] * g_dinv[d];
    int slot = atomicAdd(&g_cur[d], 1);
    g_csrc[slot] = s;
    g_cnrm[slot] = nm;
}

// ---------------- GEMM1: h = x @ W1  (N x 512 @ 512 x 64) -------------------
// 64x64 tile per block, BK=32, 256 threads, 4x4 accum per thread.
__global__ __launch_bounds__(256) void k_gemm1(const float* __restrict__ x,
                                               const float* __restrict__ W1,
                                               int N) {
    __shared__ float xs[64][32];
    __shared__ float ws[32][64];
    int tid = threadIdx.x;
    int tx = tid & 15, ty = tid >> 4;
    int row0 = blockIdx.x * 64;
    float acc[4][4] = {};

    for (int k0 = 0; k0 < IN_F; k0 += 32) {
        #pragma unroll
        for (int i = 0; i < 2; i++) {
            int f = tid * 2 + i;
            int r = f >> 3, c4 = (f & 7) * 4;
            int gr = row0 + r;
            float4 v = make_float4(0.f, 0.f, 0.f, 0.f);
            if (gr < N) v = *(const float4*)&x[(size_t)gr * IN_F + k0 + c4];
            *(float4*)&xs[r][c4] = v;
        }
        #pragma unroll
        for (int i = 0; i < 2; i++) {
            int f = tid * 2 + i;
            int r = f >> 4, c4 = (f & 15) * 4;
            *(float4*)&ws[r][c4] = *(const float4*)&W1[(k0 + r) * HID + c4];
        }
        __syncthreads();
        #pragma unroll
        for (int k = 0; k < 32; k++) {
            float a[4];
            #pragma unroll
            for (int i = 0; i < 4; i++) a[i] = xs[ty * 4 + i][k];
            float4 bv = *(float4*)&ws[k][tx * 4];
            float b[4] = {bv.x, bv.y, bv.z, bv.w};
            #pragma unroll
            for (int i = 0; i < 4; i++)
                #pragma unroll
                for (int j = 0; j < 4; j++) acc[i][j] += a[i] * b[j];
        }
        __syncthreads();
    }
    #pragma unroll
    for (int i = 0; i < 4; i++) {
        int gr = row0 + ty * 4 + i;
        if (gr < N)
            *(float4*)&g_h[(size_t)gr * HID + tx * 4] =
                make_float4(acc[i][0], acc[i][1], acc[i][2], acc[i][3]);
    }
}

// ---------------- fused layer-1 aggregation + layer-2 transform --------------
// Warp per node. acc = h[n]*dinv^2 + sum_edges h[src]*norm (CSR, no atomics),
// then h2[n] = relu(acc + b1) @ W2 via warp reduction. Replaces
// k_initagg + k_edge1 + k_layer2 and eliminates the g_agg array entirely.
__global__ __launch_bounds__(256) void k_agg1(const float* __restrict__ b1,
                                              const float* __restrict__ W2,
                                              int N) {
    __shared__ float w2s[HID * OUTF];
    __shared__ float b1s[HID];
    int tid = threadIdx.x;
    for (int i = tid; i < HID * OUTF; i += 256) w2s[i] = W2[i];
    if (tid < HID) b1s[tid] = b1[tid];
    __syncthreads();

    int n = blockIdx.x * 8 + (tid >> 5);
    if (n >= N) return;
    int lane = tid & 31;

    float di = g_dinv[n];
    float self = di * di;
    float2 hv = *(const float2*)&g_h[(size_t)n * HID + lane * 2];
    float accx = hv.x * self, accy = hv.y * self;

    int beg = g_off[n];
    int cnt = g_deg[n] - 1;
    for (int c0 = 0; c0 < cnt; c0 += 32) {
        int m = cnt - c0; if (m > 32) m = 32;
        int idx = beg + c0 + lane;
        int   msrc = (lane < m) ? g_csrc[idx] : 0;
        float mnm  = (lane < m) ? g_cnrm[idx] : 0.f;
        for (int j = 0; j < m; j++) {
            int   src = __shfl_sync(0xFFFFFFFFu, msrc, j);
            float nm  = __shfl_sync(0xFFFFFFFFu, mnm, j);
            float2 v = *(const float2*)&g_h[(size_t)src * HID + lane * 2];
            accx += v.x * nm;
            accy += v.y * nm;
        }
    }

    // relu(acc + b1) @ W2 -> 7 outputs, reduced across the warp
    float a0 = fmaxf(accx + b1s[2 * lane], 0.f);
    float a1 = fmaxf(accy + b1s[2 * lane + 1], 0.f);
    float o_[OUTF];
    #pragma unroll
    for (int o = 0; o < OUTF; o++)
        o_[o] = a0 * w2s[(2 * lane) * OUTF + o] + a1 * w2s[(2 * lane + 1) * OUTF + o];
    #pragma unroll
    for (int off = 16; off > 0; off >>= 1)
        #pragma unroll
        for (int o = 0; o < OUTF; o++)
            o_[o] += __shfl_down_sync(0xFFFFFFFFu, o_[o], off);

    if (lane == 0) {
        #pragma unroll
        for (int o = 0; o < OUTF; o++) g_h2[n * 8 + o] = o_[o];
        g_h2[n * 8 + 7] = 0.f;
    }
}

// ---------------- fused layer-2 aggregation + bias + output ------------------
// Thread per node. Replaces k_initagg2 + k_edge2 + k_final.
__global__ void k_agg2(const float* __restrict__ b2, float* __restrict__ out, int N) {
    int n = blockIdx.x * blockDim.x + threadIdx.x;
    if (n >= N) return;
    float di = g_dinv[n];
    float s = di * di;
    float4 lo = *(const float4*)&g_h2[n * 8];
    float4 hi = *(const float4*)&g_h2[n * 8 + 4];
    float a[OUTF] = {lo.x * s, lo.y * s, lo.z * s, lo.w * s,
                     hi.x * s, hi.y * s, hi.z * s};
    int beg = g_off[n];
    int cnt = g_deg[n] - 1;
    for (int i = 0; i < cnt; i++) {
        int src = g_csrc[beg + i];
        float nm = g_cnrm[beg + i];
        float4 v = *(const float4*)&g_h2[src * 8];
        float4 w = *(const float4*)&g_h2[src * 8 + 4];
        a[0] += v.x * nm; a[1] += v.y * nm; a[2] += v.z * nm; a[3] += v.w * nm;
        a[4] += w.x * nm; a[5] += w.y * nm; a[6] += w.z * nm;
    }
    #pragma unroll
    for (int o = 0; o < OUTF; o++) out[n * OUTF + o] = a[o] + b2[o];
}

// ---------------- launch -----------------------------------------------------
extern "C" void kernel_launch(void* const* d_in, const int* in_sizes, int n_in,
                              void* d_out, int out_size) {
    const float* x  = (const float*)d_in[0];
    const void*  ei = d_in[1];
    const float* W1 = (const float*)d_in[2];
    const float* b1 = (const float*)d_in[3];
    const float* W2 = (const float*)d_in[4];
    const float* b2 = (const float*)d_in[5];
    float* out = (float*)d_out;

    int N = in_sizes[0] / IN_F;
    int E = in_sizes[1] / 2;

    const int T = 256;
    k_detect<<<1, T>>>((const long long*)ei, E, N);
    k_deg_init<<<(N + T - 1) / T, T>>>(N);
    k_extract_deg<<<(E + T - 1) / T, T>>>(ei, E);
    k_scan_dinv<<<1, 1024>>>(N);
    k_scatter<<<(E + T - 1) / T, T>>>(E);

    k_gemm1<<<(N + 63) / 64, T>>>(x, W1, N);
    k_agg1<<<(N + 7) / 8, T>>>(b1, W2, N);
    k_agg2<<<(N + T - 1) / T, T>>>(b2, out, N);
}

// round 9
// speedup vs baseline: 1.6365x; 1.1340x over previous
#include <cuda_runtime.h>
#include <cuda_bf16.h>

// Problem constants (from reference setup_inputs)
#define IN_F  512
#define HID   64
#define OUTF  7
#define MAXN  50000
#define MAXE  1600000

// ---------------- scratch (device globals; no allocation allowed) -----------
__device__ __align__(16) int   g_deg[MAXN];     // degree incl. self loop
__device__ __align__(16) float g_dinv[MAXN];
__device__ __align__(16) int   g_off[MAXN];     // CSR row start (by dst)
__device__ __align__(16) int   g_cur[MAXN];     // scatter cursor
__device__ __align__(16) int   g_s32[MAXE];
__device__ __align__(16) int   g_d32[MAXE];
__device__ __align__(16) int   g_csrc[MAXE];    // CSR: src per slot
__device__ __align__(16) float g_cnrm[MAXE];    // CSR: norm per slot
__device__ __align__(16) float g_h[MAXN * HID]; // x @ W1
__device__ __align__(16) float g_h2[MAXN * 8];  // layer2 features, padded to 8
__device__ int g_is32;
__device__ int g_total;                         // CSR range allocator cursor

// ---------------- edge dtype detection --------------------------------------
// If the edge buffer is really int64, every entry is in [0, N). If it is int32
// data viewed as int64, values are >= 2^32 (or negative) almost surely within
// the first 2048 words.
__global__ void k_detect(const long long* __restrict__ ei, int E, int N) {
    if (threadIdx.x == 0) g_is32 = 0;
    __syncthreads();
    int cnt = min(2 * E, 2048);
    int bad = 0;
    for (int i = threadIdx.x; i < cnt; i += blockDim.x) {
        long long v = ei[i];
        if (v < 0 || v >= (long long)N) bad = 1;
    }
    if (bad) atomicExch(&g_is32, 1);
}

// deg starts at 1 (the self loop); also reset the range allocator
__global__ void k_deg_init(int N) {
    int i = blockIdx.x * blockDim.x + threadIdx.x;
    if (i < N) g_deg[i] = 1;
    if (i == 0) g_total = 0;
}

// extract indices + degree histogram in one pass
__global__ void k_extract_deg(const void* __restrict__ eiv, int E) {
    int e = blockIdx.x * blockDim.x + threadIdx.x;
    if (e >= E) return;
    int s, d;
    if (g_is32) {
        const int* ei = (const int*)eiv;
        s = ei[e]; d = ei[E + e];
    } else {
        const long long* ei = (const long long*)eiv;
        s = (int)ei[e]; d = (int)ei[E + e];
    }
    g_s32[e] = s;
    g_d32[e] = d;
    atomicAdd(&g_deg[d], 1);
}

// CSR range allocation WITHOUT an ordered scan: ranges need only be
// contiguous & disjoint, not in node order. Warp-aggregated atomic:
// inclusive shuffle-scan of deg-1 within the warp, one atomicAdd per warp.
// Also computes dinv in the same pass. Replaces the 42us single-block scan.
__global__ void k_offsets(int N) {
    int n = blockIdx.x * blockDim.x + threadIdx.x;
    int lane = threadIdx.x & 31;
    int deg = (n < N) ? g_deg[n] : 1;
    int e = deg - 1;
    int x = e;
    #pragma unroll
    for (int off = 1; off < 32; off <<= 1) {
        int y = __shfl_up_sync(0xFFFFFFFFu, x, off);
        if (lane >= off) x += y;
    }
    int warpsum = __shfl_sync(0xFFFFFFFFu, x, 31);
    int base = 0;
    if (lane == 31) base = atomicAdd(&g_total, warpsum);
    base = __shfl_sync(0xFFFFFFFFu, base, 31);
    if (n < N) {
        int off = base + x - e;   // exclusive prefix within warp
        g_off[n] = off;
        g_cur[n] = off;
        g_dinv[n] = rsqrtf((float)deg);
    }
}

// bin edges by dst: CSR slot <- (src, norm)
__global__ void k_scatter(int E) {
    int e = blockIdx.x * blockDim.x + threadIdx.x;
    if (e >= E) return;
    int s = g_s32[e], d = g_d32[e];
    float nm = g_dinv[s] * g_dinv[d];
    int slot = atomicAdd(&g_cur[d], 1);
    g_csrc[slot] = s;
    g_cnrm[slot] = nm;
}

// ---------------- GEMM1: h = x @ W1  (N x 512 @ 512 x 64) -------------------
// 64x64 tile per block, BK=32, 256 threads, 4x4 accum per thread.
__global__ __launch_bounds__(256) void k_gemm1(const float* __restrict__ x,
                                               const float* __restrict__ W1,
                                               int N) {
    __shared__ float xs[64][32];
    __shared__ float ws[32][64];
    int tid = threadIdx.x;
    int tx = tid & 15, ty = tid >> 4;
    int row0 = blockIdx.x * 64;
    float acc[4][4] = {};

    for (int k0 = 0; k0 < IN_F; k0 += 32) {
        #pragma unroll
        for (int i = 0; i < 2; i++) {
            int f = tid * 2 + i;
            int r = f >> 3, c4 = (f & 7) * 4;
            int gr = row0 + r;
            float4 v = make_float4(0.f, 0.f, 0.f, 0.f);
            if (gr < N) v = *(const float4*)&x[(size_t)gr * IN_F + k0 + c4];
            *(float4*)&xs[r][c4] = v;
        }
        #pragma unroll
        for (int i = 0; i < 2; i++) {
            int f = tid * 2 + i;
            int r = f >> 4, c4 = (f & 15) * 4;
            *(float4*)&ws[r][c4] = *(const float4*)&W1[(k0 + r) * HID + c4];
        }
        __syncthreads();
        #pragma unroll
        for (int k = 0; k < 32; k++) {
            float a[4];
            #pragma unroll
            for (int i = 0; i < 4; i++) a[i] = xs[ty * 4 + i][k];
            float4 bv = *(float4*)&ws[k][tx * 4];
            float b[4] = {bv.x, bv.y, bv.z, bv.w};
            #pragma unroll
            for (int i = 0; i < 4; i++)
                #pragma unroll
                for (int j = 0; j < 4; j++) acc[i][j] += a[i] * b[j];
        }
        __syncthreads();
    }
    #pragma unroll
    for (int i = 0; i < 4; i++) {
        int gr = row0 + ty * 4 + i;
        if (gr < N)
            *(float4*)&g_h[(size_t)gr * HID + tx * 4] =
                make_float4(acc[i][0], acc[i][1], acc[i][2], acc[i][3]);
    }
}

// ---------------- fused layer-1 aggregation + layer-2 transform --------------
// Warp per node. acc = h[n]*dinv^2 + sum_edges h[src]*norm (CSR, no atomics),
// then h2[n] = relu(acc + b1) @ W2 via warp reduction.
__global__ __launch_bounds__(256) void k_agg1(const float* __restrict__ b1,
                                              const float* __restrict__ W2,
                                              int N) {
    __shared__ float w2s[HID * OUTF];
    __shared__ float b1s[HID];
    int tid = threadIdx.x;
    for (int i = tid; i < HID * OUTF; i += 256) w2s[i] = W2[i];
    if (tid < HID) b1s[tid] = b1[tid];
    __syncthreads();

    int n = blockIdx.x * 8 + (tid >> 5);
    if (n >= N) return;
    int lane = tid & 31;

    float di = g_dinv[n];
    float self = di * di;
    float2 hv = *(const float2*)&g_h[(size_t)n * HID + lane * 2];
    float accx = hv.x * self, accy = hv.y * self;

    int beg = g_off[n];
    int cnt = g_deg[n] - 1;
    for (int c0 = 0; c0 < cnt; c0 += 32) {
        int m = cnt - c0; if (m > 32) m = 32;
        int idx = beg + c0 + lane;
        int   msrc = (lane < m) ? g_csrc[idx] : 0;
        float mnm  = (lane < m) ? g_cnrm[idx] : 0.f;
        #pragma unroll 4
        for (int j = 0; j < m; j++) {
            int   src = __shfl_sync(0xFFFFFFFFu, msrc, j);
            float nm  = __shfl_sync(0xFFFFFFFFu, mnm, j);
            float2 v = *(const float2*)&g_h[(size_t)src * HID + lane * 2];
            accx += v.x * nm;
            accy += v.y * nm;
        }
    }

    // relu(acc + b1) @ W2 -> 7 outputs, reduced across the warp
    float a0 = fmaxf(accx + b1s[2 * lane], 0.f);
    float a1 = fmaxf(accy + b1s[2 * lane + 1], 0.f);
    float o_[OUTF];
    #pragma unroll
    for (int o = 0; o < OUTF; o++)
        o_[o] = a0 * w2s[(2 * lane) * OUTF + o] + a1 * w2s[(2 * lane + 1) * OUTF + o];
    #pragma unroll
    for (int off = 16; off > 0; off >>= 1)
        #pragma unroll
        for (int o = 0; o < OUTF; o++)
            o_[o] += __shfl_down_sync(0xFFFFFFFFu, o_[o], off);

    if (lane == 0) {
        #pragma unroll
        for (int o = 0; o < OUTF; o++) g_h2[n * 8 + o] = o_[o];
        g_h2[n * 8 + 7] = 0.f;
    }
}

// ---------------- fused layer-2 aggregation + bias + output ------------------
// Thread per node.
__global__ void k_agg2(const float* __restrict__ b2, float* __restrict__ out, int N) {
    int n = blockIdx.x * blockDim.x + threadIdx.x;
    if (n >= N) return;
    float di = g_dinv[n];
    float s = di * di;
    float4 lo = *(const float4*)&g_h2[n * 8];
    float4 hi = *(const float4*)&g_h2[n * 8 + 4];
    float a[OUTF] = {lo.x * s, lo.y * s, lo.z * s, lo.w * s,
                     hi.x * s, hi.y * s, hi.z * s};
    int beg = g_off[n];
    int cnt = g_deg[n] - 1;
    #pragma unroll 2
    for (int i = 0; i < cnt; i++) {
        int src = g_csrc[beg + i];
        float nm = g_cnrm[beg + i];
        float4 v = *(const float4*)&g_h2[src * 8];
        float4 w = *(const float4*)&g_h2[src * 8 + 4];
        a[0] += v.x * nm; a[1] += v.y * nm; a[2] += v.z * nm; a[3] += v.w * nm;
        a[4] += w.x * nm; a[5] += w.y * nm; a[6] += w.z * nm;
    }
    #pragma unroll
    for (int o = 0; o < OUTF; o++) out[n * OUTF + o] = a[o] + b2[o];
}

// ---------------- launch -----------------------------------------------------
extern "C" void kernel_launch(void* const* d_in, const int* in_sizes, int n_in,
                              void* d_out, int out_size) {
    const float* x  = (const float*)d_in[0];
    const void*  ei = d_in[1];
    const float* W1 = (const float*)d_in[2];
    const float* b1 = (const float*)d_in[3];
    const float* W2 = (const float*)d_in[4];
    const float* b2 = (const float*)d_in[5];
    float* out = (float*)d_out;

    int N = in_sizes[0] / IN_F;
    int E = in_sizes[1] / 2;

    const int T = 256;
    k_detect<<<1, T>>>((const long long*)ei, E, N);
    k_deg_init<<<(N + T - 1) / T, T>>>(N);
    k_extract_deg<<<(E + T - 1) / T, T>>>(ei, E);
    k_offsets<<<(N + T - 1) / T, T>>>(N);
    k_scatter<<<(E + T - 1) / T, T>>>(E);

    k_gemm1<<<(N + 63) / 64, T>>>(x, W1, N);
    k_agg1<<<(N + 7) / 8, T>>>(b1, W2, N);
    k_agg2<<<(N + T - 1) / T, T>>>(b2, out, N);
}